// round 16
// baseline (speedup 1.0000x reference)
#include <cuda_runtime.h>
#include <cstdint>

// out[g, t*128 + c] = alpha[w,c] * mean_n pc[b,n,c],  g = b*4 + w, all t in
// {0,1,2,4,8}. Derivation: colsum = K.sum(axis=1) and K is symmetric, so
// P = 0.5*K/colsum + 0.5*I is column-stochastic along the SAME axis the
// mean-pool reduces; hence mean(P^t x) = mean(x) exactly for every t.
// The entire kernel/diffusion pipeline is a no-op under mean pooling.

__device__ float g_psum[4 * 16 * 128];   // (b, chunk, c) partial sums
__device__ int   g_cnt = 0;              // arrival ticket

// Single fused kernel: 64 CTAs (chunk = bx & 15, b = bx >> 4), 256 threads.
// Each CTA writes its chunk partial; the last-arriving CTA writes all
// 10240 outputs (fixed-order sums -> deterministic bits) and resets g_cnt.
__global__ void __launch_bounds__(256) fused_kernel(const float* __restrict__ pc,
                                                    const float* __restrict__ al,
                                                    float* __restrict__ out) {
    __shared__ float sh[128];
    __shared__ bool  amLast;
    int tid = threadIdx.x;
    int chunk = blockIdx.x & 15, b = blockIdx.x >> 4;
    int c = tid & 127, hf = tid >> 7;

    // partial sum over this CTA's 128-point chunk (coalesced)
    const float* X = pc + ((size_t)b * 2048 + chunk * 128) * 128;
    float acc = 0.f;
    #pragma unroll 8
    for (int n = hf; n < 128; n += 2)
        acc += X[(size_t)n * 128 + c];

    if (hf == 0) sh[c] = acc;
    __syncthreads();
    if (hf == 1)
        g_psum[(b * 16 + chunk) * 128 + c] = sh[c] + acc;

    // last-CTA election (threadfence-reduction pattern)
    __threadfence();
    __syncthreads();
    if (tid == 0)
        amLast = (atomicAdd(&g_cnt, 1) == 63);
    __syncthreads();
    if (!amLast) return;

    // final CTA: 256 threads x 2 (b,c) pairs = all 512 means -> 10240 outputs
    #pragma unroll
    for (int rep = 0; rep < 2; rep++) {
        int p  = tid + rep * 256;        // 0..511
        int bb = p >> 7, cc = p & 127;
        float s = 0.f;
        #pragma unroll
        for (int ch = 0; ch < 16; ch++)
            s += g_psum[(bb * 16 + ch) * 128 + cc];
        float mean = s * (1.0f / 2048.0f);
        #pragma unroll
        for (int w = 0; w < 4; w++) {
            float v = al[w * 128 + cc] * mean;
            float* og = out + (size_t)(bb * 4 + w) * 640 + cc;
            #pragma unroll
            for (int t = 0; t < 5; t++)
                og[t * 128] = v;
        }
    }
    if (tid == 0) g_cnt = 0;             // reset for graph replay
}

// ---------------------------------------------------------------------------
extern "C" void kernel_launch(void* const* d_in, const int* in_sizes, int n_in,
                              void* d_out, int out_size) {
    const float* pc = (const float*)d_in[0];   // point_clouds [4,2048,128]
    const float* al = (const float*)d_in[1];   // alphas [4,128]
    float* out = (float*)d_out;                // [4, 2560] fp32

    fused_kernel<<<64, 256>>>(pc, al, out);
}

// round 17
// speedup vs baseline: 1.0808x; 1.0808x over previous
#include <cuda_runtime.h>
#include <cstdint>

// out[g, t*128 + c] = alpha[w,c] * mean_n pc[b,n,c],  g = b*4 + w, all t in
// {0,1,2,4,8}. Derivation: colsum = K.sum(axis=1) and K is symmetric, so
// P = 0.5*K/colsum + 0.5*I is column-stochastic along the SAME axis the
// mean-pool reduces; hence mean(P^t x) = mean(x) exactly for every t.
// The entire kernel/diffusion pipeline is a no-op under mean pooling.

__device__ float4 g_psum4[4 * 16 * 32];   // (b, chunk, c4) partial sums

__device__ __forceinline__ float4 f4add(float4 a, float4 b) {
    return make_float4(a.x + b.x, a.y + b.y, a.z + b.z, a.w + b.w);
}

// ---------------------------------------------------------------------------
// Kernel 1: partial sums over 128-row chunks, float4-vectorized.
// grid (16 chunks, 4 clouds), 256 threads: j = tid&31 (float4 column slot),
// rg = tid>>5 (row group); each thread sums rows rg, rg+8, ..., rg+120.
// ---------------------------------------------------------------------------
__global__ void __launch_bounds__(256) psum_kernel(const float4* __restrict__ pc4) {
    __shared__ float4 sh[256];
    int tid = threadIdx.x;
    int chunk = blockIdx.x, b = blockIdx.y;
    int j = tid & 31, rg = tid >> 5;

    // pc row-major: row stride = 32 float4
    const float4* X = pc4 + ((size_t)b * 2048 + chunk * 128) * 32 + j;
    float4 acc = make_float4(0.f, 0.f, 0.f, 0.f);
    #pragma unroll
    for (int k = 0; k < 16; k++)
        acc = f4add(acc, X[(size_t)(rg + 8 * k) * 32]);

    sh[tid] = acc;
    __syncthreads();
    if (tid < 32) {
        float4 s = sh[j];
        #pragma unroll
        for (int g8 = 1; g8 < 8; g8++)
            s = f4add(s, sh[j + 32 * g8]);
        g_psum4[(b * 16 + chunk) * 32 + j] = s;
    }
}

// ---------------------------------------------------------------------------
// Kernel 2: all 2560 float4 outputs. grid 10 x 256 threads.
// p -> g = p/160, slot = p%160, t = slot/32 (unused: value same for all t),
// c4 = slot%32.
// ---------------------------------------------------------------------------
__global__ void __launch_bounds__(256) write_kernel(const float4* __restrict__ al4,
                                                    float4* __restrict__ out4) {
    int p = blockIdx.x * 256 + threadIdx.x;    // 0..2559
    int g = p / 160;
    int c4 = p & 31;                            // slot%32 == p%32 (160%32==0)
    int b = g >> 2, w = g & 3;

    float4 s = make_float4(0.f, 0.f, 0.f, 0.f);
    #pragma unroll
    for (int ch = 0; ch < 16; ch++)
        s = f4add(s, g_psum4[(b * 16 + ch) * 32 + c4]);

    float4 a = al4[w * 32 + c4];
    const float inv = 1.0f / 2048.0f;
    out4[p] = make_float4(a.x * s.x * inv, a.y * s.y * inv,
                          a.z * s.z * inv, a.w * s.w * inv);
}

// ---------------------------------------------------------------------------
extern "C" void kernel_launch(void* const* d_in, const int* in_sizes, int n_in,
                              void* d_out, int out_size) {
    const float4* pc4 = (const float4*)d_in[0];   // point_clouds [4,2048,128]
    const float4* al4 = (const float4*)d_in[1];   // alphas [4,128]
    float4* out4 = (float4*)d_out;                // [4,2560] fp32

    dim3 pgrid(16, 4);
    psum_kernel<<<pgrid, 256>>>(pc4);
    write_kernel<<<10, 256>>>(al4, out4);
}